// round 16
// baseline (speedup 1.0000x reference)
#include <cuda_runtime.h>
#include <cuda_bf16.h>
#include <cstdint>
#include <stdint.h>
#include <math.h>

#define H      1024
#define FF     4096
#define E      8
#define T_MAX  8192
#define NROWS  (T_MAX * 2)
#define NROWSP 18432          // padded rows (per-expert base aligned to 256)
#define KC     32
#define TB     8192
#define NKC_H  (H / KC)       // 32  (== 0 mod 8)
#define NKC_F  (FF / KC)      // 128 (== 0 mod 8)
#define NST    4
#define NCTA   148

#if defined(__CUDA_ARCH_FEAT_SM103_ALL) || defined(__CUDA_ARCH_FEAT_SM100_ALL)
#define TC_OK 1
#else
#define TC_OK 0
#endif

// ---------------- device scratch ----------------
__device__ int   g_counts[E];
__device__ int   g_base[E];
__device__ int   g_pbase[E];
__device__ int   g_jb13[E];
__device__ int   g_J13;
__device__ int   g_jb2[E];
__device__ int   g_J2;
__device__ int   g_rdone;
__device__ int   g_list[E * T_MAX];
__device__ float g_wts[T_MAX * 2];
__device__ __nv_bfloat16 g_ax_hi[(size_t)NROWSP * H];
__device__ __nv_bfloat16 g_ax_lo[(size_t)NROWSP * H];
__device__ __nv_bfloat16 g_w1h[(size_t)E * FF * H];
__device__ __nv_bfloat16 g_w1l[(size_t)E * FF * H];
__device__ __nv_bfloat16 g_w3h[(size_t)E * FF * H];
__device__ __nv_bfloat16 g_w3l[(size_t)E * FF * H];
__device__ __nv_bfloat16 g_w2h[(size_t)E * H * FF];
__device__ __nv_bfloat16 g_w2l[(size_t)E * H * FF];
__device__ __nv_bfloat16 g_act_hi[(size_t)NROWSP * FF];
__device__ __nv_bfloat16 g_act_lo[(size_t)NROWSP * FF];
__device__ float g_ybuf[(size_t)NROWS * H];

// ---------------- PTX helpers ----------------
__device__ __forceinline__ uint32_t smem_u32(const void* p) {
    uint32_t a;
    asm("{ .reg .u64 t; cvta.to.shared.u64 t, %1; cvt.u32.u64 %0, t; }" : "=r"(a) : "l"(p));
    return a;
}
__device__ __forceinline__ uint32_t cta_rank() {
    uint32_t r; asm("mov.u32 %0, %%cluster_ctarank;" : "=r"(r)); return r;
}
#define MBAR_INIT(a, c) asm volatile("mbarrier.init.shared.b64 [%0], %1;" :: "r"((uint32_t)(a)), "r"((uint32_t)(c)) : "memory")
#define MBAR_EXPECT(a, n) asm volatile("mbarrier.arrive.expect_tx.shared.b64 _, [%0], %1;" :: "r"((uint32_t)(a)), "r"((uint32_t)(n)) : "memory")
#define MBAR_ARRIVE(a) asm volatile("mbarrier.arrive.shared.b64 _, [%0];" :: "r"((uint32_t)(a)) : "memory")
#define ARRIVE_REMOTE0(local) asm volatile("{\n\t.reg .b32 r;\n\tmapa.shared::cluster.u32 r, %0, 0;\n\tmbarrier.arrive.shared::cluster.b64 _, [r];\n\t}" :: "r"((uint32_t)(local)) : "memory")
#define CLUSTER_SYNC() do { \
    asm volatile("barrier.cluster.arrive.aligned;" ::: "memory"); \
    asm volatile("barrier.cluster.wait.aligned;" ::: "memory"); \
} while (0)
#define MBAR_WAIT(a, ph) do { \
    uint32_t _m = (uint32_t)(a), _p = (uint32_t)(ph), _d; \
    asm volatile("{\n\t.reg .pred p;\n\tmbarrier.try_wait.parity.acquire.cta.shared::cta.b64 p, [%1], %2;\n\tselp.b32 %0,1,0,p;\n\t}" \
        : "=r"(_d) : "r"(_m), "r"(_p) : "memory"); \
    if (!_d) { asm volatile("{\n\t.reg .pred P1;\n\tWL_%=:\n\t" \
        "mbarrier.try_wait.parity.acquire.cta.shared::cta.b64 P1, [%0], %1, 0x989680;\n\t" \
        "@P1 bra.uni WD_%=;\n\tbra.uni WL_%=;\n\tWD_%=:\n\t}" :: "r"(_m), "r"(_p) : "memory"); } \
} while (0)

#if TC_OK
#define BULK(d, s, mb) asm volatile( \
    "cp.async.bulk.shared::cta.global.mbarrier::complete_tx::bytes [%0], [%1], %2, [%3];" \
    :: "r"((uint32_t)(d)), "l"(s), "r"(8192u), "r"((uint32_t)(mb)) : "memory")
#define TC_ALLOC_CG2(sa, n)   asm volatile("tcgen05.alloc.cta_group::2.sync.aligned.shared::cta.b32 [%0], %1;" :: "r"((uint32_t)(sa)), "r"((uint32_t)(n)) : "memory")
#define TC_DEALLOC_CG2(tm, n) asm volatile("tcgen05.dealloc.cta_group::2.sync.aligned.b32 %0, %1;" :: "r"(tm), "r"((uint32_t)(n)))
#define TC_RELINQ_CG2()       asm volatile("tcgen05.relinquish_alloc_permit.cta_group::2.sync.aligned;")
#define TC_COMMIT_MC2(mb, mask) asm volatile( \
    "tcgen05.commit.cta_group::2.mbarrier::arrive::one.shared::cluster.multicast::cluster.b64 [%0], %1;" \
    :: "r"((uint32_t)(mb)), "h"((uint16_t)(mask)) : "memory")
#define TC_FENCE_AFTER()  asm volatile("tcgen05.fence::after_thread_sync;" ::: "memory")
#define TC_FENCE_BEFORE() asm volatile("tcgen05.fence::before_thread_sync;" ::: "memory")
#define TC_WAIT_LD()      asm volatile("tcgen05.wait::ld.sync.aligned;" ::: "memory")
#define TC_LD_X32(r, ta) \
    asm volatile("tcgen05.ld.sync.aligned.32x32b.x32.b32 " \
        "{%0,%1,%2,%3,%4,%5,%6,%7,%8,%9,%10,%11,%12,%13,%14,%15," \
        "%16,%17,%18,%19,%20,%21,%22,%23,%24,%25,%26,%27,%28,%29,%30,%31}, [%32];" \
        : "=r"((r)[0]), "=r"((r)[1]), "=r"((r)[2]), "=r"((r)[3]), "=r"((r)[4]), "=r"((r)[5]), "=r"((r)[6]), "=r"((r)[7]), \
          "=r"((r)[8]), "=r"((r)[9]), "=r"((r)[10]), "=r"((r)[11]), "=r"((r)[12]), "=r"((r)[13]), "=r"((r)[14]), "=r"((r)[15]), \
          "=r"((r)[16]), "=r"((r)[17]), "=r"((r)[18]), "=r"((r)[19]), "=r"((r)[20]), "=r"((r)[21]), "=r"((r)[22]), "=r"((r)[23]), \
          "=r"((r)[24]), "=r"((r)[25]), "=r"((r)[26]), "=r"((r)[27]), "=r"((r)[28]), "=r"((r)[29]), "=r"((r)[30]), "=r"((r)[31]) \
        : "r"(ta))

static constexpr uint64_t DESC_SW64 =
    (uint64_t(4) << 61) | (uint64_t(1) << 46) | (uint64_t(32) << 32) | (uint64_t(1) << 16);
#define MK_DESC(a) (DESC_SW64 | ((uint64_t)((a) >> 4) & 0x3FFF))
#define IDESC_CG2 ((1u << 4) | (1u << 7) | (1u << 10) | (32u << 17) | (16u << 24))

__device__ __forceinline__ void mma_cg2(uint32_t d, uint64_t a, uint64_t b, uint32_t en) {
    asm volatile("{\n\t.reg .pred p;\n\tsetp.ne.u32 p, %4, 0;\n\t"
        "tcgen05.mma.cta_group::2.kind::f16 [%0], %1, %2, %3, {%5,%5,%5,%5,%5,%5,%5,%5}, p;\n\t}"
        :: "r"(d), "l"(a), "l"(b), "r"(IDESC_CG2), "r"(en), "r"(0u) : "memory");
}
#endif  // TC_OK

__device__ __forceinline__ uint32_t pack_hi(float a, float b, uint32_t& lo) {
    __nv_bfloat16 h0 = __float2bfloat16(a), h1 = __float2bfloat16(b);
    __nv_bfloat16 l0 = __float2bfloat16(a - __bfloat162float(h0));
    __nv_bfloat16 l1 = __float2bfloat16(b - __bfloat162float(h1));
    lo = (uint32_t)__bfloat16_as_ushort(l0) | ((uint32_t)__bfloat16_as_ushort(l1) << 16);
    return (uint32_t)__bfloat16_as_ushort(h0) | ((uint32_t)__bfloat16_as_ushort(h1) << 16);
}

__device__ __forceinline__ void split8_body(const float* __restrict__ src,
                                            __nv_bfloat16* __restrict__ hi,
                                            __nv_bfloat16* __restrict__ lo,
                                            long i, int K, int nkc) {
    long f = i * 8;
    int row = (int)(f / K), k0 = (int)(f % K);
    int kc = k0 >> 5, c = (k0 & 31) >> 3;
    int rr = row & 127, tr = row >> 7;
    size_t off = ((size_t)tr * nkc + kc) * TB + (size_t)rr * 64 + ((c ^ ((rr >> 1) & 3)) << 4);
    const float4* s4 = (const float4*)(src + f);
    float4 a = s4[0], b = s4[1];
    float v[8] = {a.x, a.y, a.z, a.w, b.x, b.y, b.z, b.w};
    uint32_t ph[4], pl[4];
#pragma unroll
    for (int j = 0; j < 4; j++) ph[j] = pack_hi(v[2 * j], v[2 * j + 1], pl[j]);
    *(uint4*)((char*)hi + off) = make_uint4(ph[0], ph[1], ph[2], ph[3]);
    *(uint4*)((char*)lo + off) = make_uint4(pl[0], pl[1], pl[2], pl[3]);
}

// ---------------- fused split kernel + counts zeroing ----------------
__global__ void k_split_all(const float* __restrict__ w1, const float* __restrict__ w3,
                            const float* __restrict__ w2) {
    if (blockIdx.x == 0 && threadIdx.x < E) g_counts[threadIdx.x] = 0;
    if (blockIdx.x == 0 && threadIdx.x == 0) g_rdone = 0;
    const long n8 = (long)E * FF * H / 8;
    const long stride = (long)gridDim.x * blockDim.x;
    long i0 = (long)blockIdx.x * blockDim.x + threadIdx.x;
    for (long i = i0; i < n8; i += stride) {
        split8_body(w1, g_w1h, g_w1l, i, H, NKC_H);
        split8_body(w3, g_w3h, g_w3l, i, H, NKC_H);
        split8_body(w2, g_w2h, g_w2l, i, FF, NKC_F);
    }
}

// ---------------- router (+ last-block prefix/base) ----------------
__global__ void k_router(const float* __restrict__ x, const float* __restrict__ gate,
                         float* __restrict__ logits_out, int T) {
    __shared__ float sg[E * H];
    for (int i = threadIdx.x; i < E * H; i += blockDim.x) sg[i] = gate[i];
    __syncthreads();
    int warp = threadIdx.x >> 5, lane = threadIdx.x & 31;
    int t = blockIdx.x * 8 + warp;
    if (t < T) {
        const float* xr = x + (size_t)t * H;
        float acc[E];
#pragma unroll
        for (int e = 0; e < E; e++) acc[e] = 0.f;
        for (int k = lane; k < H; k += 32) {
            float xv = xr[k];
#pragma unroll
            for (int e = 0; e < E; e++) acc[e] += xv * sg[e * H + k];
        }
#pragma unroll
        for (int e = 0; e < E; e++)
#pragma unroll
            for (int o = 16; o > 0; o >>= 1) acc[e] += __shfl_down_sync(0xffffffffu, acc[e], o);
        if (lane == 0) {
#pragma unroll
            for (int e = 0; e < E; e++) logits_out[(size_t)t * E + e] = acc[e];
            int e0 = 0; float l0 = acc[0];
#pragma unroll
            for (int e = 1; e < E; e++) if (acc[e] > l0) { l0 = acc[e]; e0 = e; }
            int e1 = -1; float l1 = -1e30f;
#pragma unroll
            for (int e = 0; e < E; e++) if (e != e0 && acc[e] > l1) { l1 = acc[e]; e1 = e; }
            float s = 0.f, pe[E];
#pragma unroll
            for (int e = 0; e < E; e++) { pe[e] = expf(acc[e] - l0); s += pe[e]; }
            float p0 = pe[e0] / s, p1 = pe[e1] / s;
            float inv = 1.f / (p0 + p1);
            int q0 = atomicAdd(&g_counts[e0], 1);
            g_list[e0 * T_MAX + q0] = (t << 1);
            g_wts[(t << 1)] = p0 * inv;
            int q1 = atomicAdd(&g_counts[e1], 1);
            g_list[e1 * T_MAX + q1] = (t << 1) | 1;
            g_wts[(t << 1) | 1] = p1 * inv;
        }
    }
    __syncthreads();
    if (threadIdx.x == 0) {
        __threadfence();
        int done = atomicAdd(&g_rdone, 1);
        if (done == (int)gridDim.x - 1) {
            int s = 0, ps = 0, j13 = 0, j2 = 0;
#pragma unroll
            for (int e = 0; e < E; e++) {
                g_base[e] = s;  g_pbase[e] = ps;
                g_jb13[e] = j13; g_jb2[e] = j2;
                int np = (g_counts[e] + 255) >> 8;   // 256-row blocks
                j13 += np * (FF / 128);
                j2  += np * (H / 256);
                s += g_counts[e];
                ps += (g_counts[e] + 255) & ~255;
            }
            g_J13 = j13;  g_J2 = j2;
        }
    }
}

// gather x rows into expert-grouped (padded) tiled hi/lo
__global__ void k_gather(const float* __restrict__ x, int total) {
    int g = blockIdx.x;
    if (g >= total) return;
    int e = 0;
#pragma unroll
    for (int k = 1; k < E; k++) if (g >= g_base[k]) e = k;
    int pos = g - g_base[e];
    int tok = g_list[e * T_MAX + pos] >> 1;
    int prow = g_pbase[e] + pos;
    int rr = prow & 127, tr = prow >> 7;
    int tid = threadIdx.x;
    int kc = tid >> 2, c = tid & 3;
    size_t off = ((size_t)tr * NKC_H + kc) * TB + (size_t)rr * 64 + ((c ^ ((rr >> 1) & 3)) << 4);
    const float4* src = (const float4*)(x + (size_t)tok * H + tid * 8);
    float4 a = src[0], b = src[1];
    uint32_t pl0, pl1, pl2, pl3;
    uint32_t ph0 = pack_hi(a.x, a.y, pl0);
    uint32_t ph1 = pack_hi(a.z, a.w, pl1);
    uint32_t ph2 = pack_hi(b.x, b.y, pl2);
    uint32_t ph3 = pack_hi(b.z, b.w, pl3);
    *(uint4*)((char*)g_ax_hi + off) = make_uint4(ph0, ph1, ph2, ph3);
    *(uint4*)((char*)g_ax_lo + off) = make_uint4(pl0, pl1, pl2, pl3);
}

#define SM_T 1024
// barrier layout: full[4]@8, mmadone[4]@48, acc_full[2]@80, epi_free[2]@96
#define MB_FULL(b) (8 + (b) * 8)
#define MB_DONE(b) (48 + (b) * 8)
#define MB_ACC(b)  (80 + (b) * 8)
#define MB_EPI(b)  (96 + (b) * 8)

#if TC_OK
// one stage fill (4 tiles, 32KB): A hi/lo (this CTA's 128 rows) + W hi/lo
__device__ __forceinline__ void bulk4(uint32_t sb, int buf,
    const __nv_bfloat16* Ah, const __nv_bfloat16* Al, int trA, int nkcA,
    const __nv_bfloat16* Wh, const __nv_bfloat16* Wl, int trW, int nkcW, int kc) {
    uint32_t mb = sb + MB_FULL(buf);
    uint32_t dst = sb + SM_T + buf * 4 * TB;
    size_t a0 = ((size_t)trA * nkcA + kc) * TB;
    size_t w  = ((size_t)trW * nkcW + kc) * TB;
    BULK(dst + 0 * TB, (const char*)Ah + a0, mb);
    BULK(dst + 1 * TB, (const char*)Al + a0, mb);
    BULK(dst + 2 * TB, (const char*)Wh + w, mb);
    BULK(dst + 3 * TB, (const char*)Wl + w, mb);
}

// tid0-only mainloop into accumulator `acc` (256 cols)
__device__ void mainloop4(uint32_t sb, uint32_t acc, int NCH, int rank,
    const __nv_bfloat16* Ah, const __nv_bfloat16* Al, int trA, int nkcA,
    const __nv_bfloat16* Wh, const __nv_bfloat16* Wl, int trW, int nkcW) {
    for (int i = 0; i < NCH; i++) {
        int b = i & (NST - 1);
        MBAR_WAIT(sb + MB_FULL(b), (i >> 2) & 1);
        MBAR_EXPECT(sb + MB_FULL(b), 4 * TB);
        if (rank == 0) {
            uint32_t tb = sb + SM_T + b * 4 * TB;
            uint64_t dAh = MK_DESC(tb),          dAl = MK_DESC(tb + TB);
            uint64_t dWh = MK_DESC(tb + 2 * TB), dWl = MK_DESC(tb + 3 * TB);
#pragma unroll
            for (int ks = 0; ks < 2; ks++) {
                uint64_t o = (uint64_t)(2 * ks);
                uint32_t en = (i > 0 || ks > 0) ? 1u : 0u;
                mma_cg2(acc, dAh + o, dWh + o, en);
                mma_cg2(acc, dAh + o, dWl + o, 1);
                mma_cg2(acc, dAl + o, dWh + o, 1);
            }
            TC_COMMIT_MC2(sb + MB_DONE(b), 0x3);
        } else {
            ARRIVE_REMOTE0(sb + MB_FULL(b));
        }
        if (i + 3 < NCH) {
            int nb = (i + 3) & (NST - 1);
            if (i >= 1) MBAR_WAIT(sb + MB_DONE(nb), ((i - 1) >> 2) & 1);
            bulk4(sb, nb, Ah, Al, trA, nkcA, Wh, Wl, trW, nkcW, i + 3);
        }
    }
    for (int c = NCH - NST; c < NCH; c++)
        MBAR_WAIT(sb + MB_DONE(c & (NST - 1)), (c >> 2) & 1);
}

__device__ __forceinline__ int job_e(const int* jb, int j) {
    int e = 0;
#pragma unroll
    for (int k = 1; k < E; k++) if (j >= jb[k]) e = k;
    return e;
}

__device__ __forceinline__ void pf13(uint32_t sb, int j, int rank) {
    int e = job_e(g_jb13, j);
    int local = j - g_jb13[e];
    int trA = (g_pbase[e] + (local >> 5) * 256 + rank * 128) >> 7;
    int trW = (e * FF + (local & 31) * 128) >> 7;
    const __nv_bfloat16* Wh = rank ? g_w3h : g_w1h;
    const __nv_bfloat16* Wl = rank ? g_w3l : g_w1l;
    bulk4(sb, 0, g_ax_hi, g_ax_lo, trA, NKC_H, Wh, Wl, trW, NKC_H, 0);
    bulk4(sb, 1, g_ax_hi, g_ax_lo, trA, NKC_H, Wh, Wl, trW, NKC_H, 1);
    bulk4(sb, 2, g_ax_hi, g_ax_lo, trA, NKC_H, Wh, Wl, trW, NKC_H, 2);
}

__device__ __forceinline__ void pf2(uint32_t sb, int j, int rank) {
    int e = job_e(g_jb2, j);
    int local = j - g_jb2[e];
    int trA = (g_pbase[e] + (local >> 2) * 256 + rank * 128) >> 7;
    int trW = (e * H + (local & 3) * 256 + rank * 128) >> 7;
    bulk4(sb, 0, g_act_hi, g_act_lo, trA, NKC_F, g_w2h, g_w2l, trW, NKC_F, 0);
    bulk4(sb, 1, g_act_hi, g_act_lo, trA, NKC_F, g_w2h, g_w2l, trW, NKC_F, 1);
    bulk4(sb, 2, g_act_hi, g_act_lo, trA, NKC_F, g_w2h, g_w2l, trW, NKC_F, 2);
}

__device__ __forceinline__ void init_bars(uint32_t sb, int rank) {
#pragma unroll
    for (int b = 0; b < NST; b++) {
        MBAR_INIT(sb + MB_FULL(b), rank == 0 ? 2 : 1);
        MBAR_INIT(sb + MB_DONE(b), 1);
        MBAR_EXPECT(sb + MB_FULL(b), 4 * TB);
    }
#pragma unroll
    for (int b = 0; b < 2; b++) {
        MBAR_INIT(sb + MB_ACC(b), 1);
        MBAR_INIT(sb + MB_EPI(b), 8);   // 4 local + 4 remote epilogue warps
    }
}
#endif

// ---------------- persistent cg2 GEMM13: pair BM=256, BN=128, dual-accum ----------------
__global__ __launch_bounds__(256, 1) __cluster_dims__(2, 1, 1) void k_mma13() {
#if TC_OK
    int rank = (int)cta_rank();
    int pair = blockIdx.x >> 1;
    int npair = gridDim.x >> 1;
    extern __shared__ char sm[];
    uint32_t sb = smem_u32(sm);
    int tid = threadIdx.x, wid = tid >> 5, lid = tid & 31;

    if (wid == 0) TC_ALLOC_CG2(sb, 512);
    if (tid == 0) init_bars(sb, rank);
    __syncthreads();
    CLUSTER_SYNC();
    uint32_t tm;
    asm volatile("ld.shared.b32 %0, [%1];" : "=r"(tm) : "r"(sb));

    int J = g_J13;
    if (tid == 0 && pair < J) pf13(sb, pair, rank);

    int jj = 0;
    for (int j = pair; j < J; j += npair, jj++) {
        int e = job_e(g_jb13, j);
        int local = j - g_jb13[e];
        int cnt = g_counts[e];
        int row0 = (local >> 5) * 256;
        int n0 = (local & 31) * 128;
        int rbase = g_pbase[e] + row0 + rank * 128;
        uint32_t acc = tm + (jj & 1) * 256;

        if (tid == 0) {
            if (rank == 0 && jj >= 2) {
                MBAR_WAIT(sb + MB_EPI(jj & 1), ((jj >> 1) - 1) & 1);
                TC_FENCE_AFTER();
            }
            const __nv_bfloat16* Wh = rank ? g_w3h : g_w1h;
            const __nv_bfloat16* Wl = rank ? g_w3l : g_w1l;
            mainloop4(sb, acc, NKC_H, rank, g_ax_hi, g_ax_lo, rbase >> 7, NKC_H,
                      Wh, Wl, (e * FF + n0) >> 7, NKC_H);
            MBAR_ARRIVE(sb + MB_ACC(jj & 1));
            int jn = j + npair;
            if (jn < J) pf13(sb, jn, rank);
        } else if (wid >= 4) {
            // epilogue crew (warps 4-7 -> subpartitions 0-3)
            MBAR_WAIT(sb + MB_ACC(jj & 1), (jj >> 1) & 1);
            TC_FENCE_AFTER();
            int sub = wid - 4;
            int lrow = sub * 32 + lid;
            bool valid = (row0 + rank * 128 + lrow) < cnt;
            int prow = rbase + lrow;
            int rr = prow & 127, tr = prow >> 7, sw = (rr >> 1) & 3;
#pragma unroll
            for (int c0 = 0; c0 < 128; c0 += 32) {
                uint32_t d1[32], d3[32];
                TC_LD_X32(d1, acc + c0);
                TC_LD_X32(d3, acc + 128 + c0);
                TC_WAIT_LD();
                if (valid) {
                    uint32_t ph[16], pl[16];
#pragma unroll
                    for (int jq = 0; jq < 16; jq++) {
                        float h0 = __uint_as_float(d1[2 * jq]),     v0 = __uint_as_float(d3[2 * jq]);
                        float h1 = __uint_as_float(d1[2 * jq + 1]), v1 = __uint_as_float(d3[2 * jq + 1]);
                        float a0 = (h0 / (1.f + __expf(-h0))) * v0;
                        float a1 = (h1 / (1.f + __expf(-h1))) * v1;
                        ph[jq] = pack_hi(a0, a1, pl[jq]);
                    }
                    int kc = (n0 >> 5) + (c0 >> 5);
                    size_t tbo = ((size_t)tr * NKC_F + kc) * TB + (size_t)rr * 64;
#pragma unroll
                    for (int q = 0; q < 4; q++) {
                        size_t o = tbo + ((q ^ sw) << 4);
                        *(uint4*)((char*)g_act_hi + o) = make_uint4(ph[4 * q], ph[4 * q + 1], ph[4 * q + 2], ph[4 * q + 3]);
                        *(uint4*)((char*)g_act_lo + o) = make_uint4(pl[4 * q], pl[4 * q + 1], pl[4 * q + 2], pl[4 * q + 3]);
                    }
                }
            }
            TC_FENCE_BEFORE();
            if (lid == 0) {
                if (rank == 0) MBAR_ARRIVE(sb + MB_EPI(jj & 1));
                else           ARRIVE_REMOTE0(sb + MB_EPI(jj & 1));
            }
        }
    }
    __syncthreads();
    if (wid == 0) { TC_RELINQ_CG2(); TC_DEALLOC_CG2(tm, 512); }
    CLUSTER_SYNC();
#endif
}

// ---------------- persistent cg2 GEMM2: pair BM=256, BN=256, dual-accum ----------------
__global__ __launch_bounds__(256, 1) __cluster_dims__(2, 1, 1) void k_mma2() {
#if TC_OK
    int rank = (int)cta_rank();
    int pair = blockIdx.x >> 1;
    int npair = gridDim.x >> 1;
    extern __shared__ char sm[];
    uint32_t sb = smem_u32(sm);
    int tid = threadIdx.x, wid = tid >> 5, lid = tid & 31;

    if (wid == 0) TC_ALLOC_CG2(sb, 512);
    if (tid == 0) init_bars(sb, rank);
    __syncthreads();
    CLUSTER_SYNC();
    uint32_t tm;
    asm volatile("ld.shared.b32 %0, [%1];" : "=r"(tm) : "r"(sb));

    int J = g_J2;
    if (tid == 0 && pair < J) pf2(sb, pair, rank);

    int jj = 0;
    for (int j = pair; j < J; j += npair, jj++) {
        int e = job_e(g_jb2, j);
        int local = j - g_jb2[e];
        int cnt = g_counts[e];
        int row0 = (local >> 2) * 256;
        int n0 = (local & 3) * 256;
        uint32_t acc = tm + (jj & 1) * 256;

        if (tid == 0) {
            if (rank == 0 && jj >= 2) {
                MBAR_WAIT(sb + MB_EPI(jj & 1), ((jj >> 1) - 1) & 1);
                TC_FENCE_AFTER();
            }
            mainloop4(sb, acc, NKC_F, rank, g_act_hi, g_act_lo,
                      (g_pbase[e] + row0 + rank * 128) >> 7, NKC_F,
                      g_w2h, g_w2l, (e * H + n0 + rank * 128) >> 7, NKC_F);
            MBAR_ARRIVE(sb + MB_ACC(jj & 1));
            int jn = j + npair;
            if (jn < J) pf2(sb, jn, rank);
        } else if (wid >= 4) {
            MBAR_WAIT(sb + MB_ACC(jj & 1), (jj >> 1) & 1);
            TC_FENCE_AFTER();
            int sub = wid - 4;
            int lrow = sub * 32 + lid;
            bool valid = (row0 + rank * 128 + lrow) < cnt;
            int ts = 0; float w = 0.f;
            if (valid) { ts = g_list[e * T_MAX + row0 + rank * 128 + lrow]; w = g_wts[ts]; }
            float* yrow = g_ybuf + (size_t)ts * H + n0;
#pragma unroll
            for (int c0 = 0; c0 < 256; c0 += 32) {
                uint32_t d[32];
                TC_LD_X32(d, acc + c0);
                TC_WAIT_LD();
                if (valid) {
                    float4* dst = (float4*)(yrow + c0);
#pragma unroll
                    for (int q = 0; q < 8; q++)
                        dst[q] = make_float4(w * __uint_as_float(d[4 * q]), w * __uint_as_float(d[4 * q + 1]),
                                             w * __uint_as_float(d[4 * q + 2]), w * __uint_as_float(d[4 * q + 3]));
                }
            }
            TC_FENCE_BEFORE();
            if (lid == 0) {
                if (rank == 0) MBAR_ARRIVE(sb + MB_EPI(jj & 1));
                else           ARRIVE_REMOTE0(sb + MB_EPI(jj & 1));
            }
        }
    }
    __syncthreads();
    if (wid == 0) { TC_RELINQ_CG2(); TC_DEALLOC_CG2(tm, 512); }
    CLUSTER_SYNC();
#endif
}

__global__ void k_combine(float* __restrict__ out, int T) {
    int i = blockIdx.x * blockDim.x + threadIdx.x;
    int total = T * (H / 4);
    if (i >= total) return;
    int t = i / (H / 4);
    int h4 = i - t * (H / 4);
    const float4* yb = (const float4*)g_ybuf;
    float4 a = yb[(size_t)(2 * t) * (H / 4) + h4];
    float4 b = yb[(size_t)(2 * t + 1) * (H / 4) + h4];
    ((float4*)out)[i] = make_float4(a.x + b.x, a.y + b.y, a.z + b.z, a.w + b.w);
}

// ---------------- launch ----------------
extern "C" void kernel_launch(void* const* d_in, const int* in_sizes, int n_in,
                              void* d_out, int out_size) {
    const float* x;
    const float* gate;
    if (in_sizes[0] > in_sizes[1]) { x = (const float*)d_in[0]; gate = (const float*)d_in[1]; }
    else                           { gate = (const float*)d_in[0]; x = (const float*)d_in[1]; }
    const float* w1 = (const float*)d_in[2];
    const float* w2 = (const float*)d_in[3];
    const float* w3 = (const float*)d_in[4];
    int T = (in_sizes[0] > in_sizes[1] ? in_sizes[0] : in_sizes[1]) / H;

    float* out = (float*)d_out;
    float* logits_out = out + (size_t)T * H;

    int smem = SM_T + NST * 4 * TB;  // 132,096
    cudaFuncSetAttribute(k_mma13, cudaFuncAttributeMaxDynamicSharedMemorySize, smem);
    cudaFuncSetAttribute(k_mma2,  cudaFuncAttributeMaxDynamicSharedMemorySize, smem);

    long n8 = (long)E * FF * H / 8;
    int sblk = (int)((n8 + 255) / 256);
    if (sblk > 16384) sblk = 16384;
    k_split_all<<<sblk, 256>>>(w1, w3, w2);

    k_router<<<(T + 7) / 8, 256>>>(x, gate, logits_out, T);
    k_gather<<<2 * T, 128>>>(x, 2 * T);

    cudaLaunchAttribute attrs[1];
    attrs[0].id = cudaLaunchAttributeClusterDimension;
    attrs[0].val.clusterDim.x = 2; attrs[0].val.clusterDim.y = 1; attrs[0].val.clusterDim.z = 1;

    cudaLaunchConfig_t cfg13 = {};
    cfg13.gridDim  = dim3(NCTA, 1, 1);
    cfg13.blockDim = dim3(256, 1, 1);
    cfg13.dynamicSmemBytes = smem;
    cfg13.attrs = attrs; cfg13.numAttrs = 1;
    cudaLaunchKernelEx(&cfg13, k_mma13);

    cudaLaunchConfig_t cfg2 = {};
    cfg2.gridDim  = dim3(NCTA, 1, 1);
    cfg2.blockDim = dim3(256, 1, 1);
    cfg2.dynamicSmemBytes = smem;
    cfg2.attrs = attrs; cfg2.numAttrs = 1;
    cudaLaunchKernelEx(&cfg2, k_mma2);

    k_combine<<<(T * (H / 4) + 255) / 256, 256>>>(out, T);
}

// round 17
// speedup vs baseline: 1.2005x; 1.2005x over previous
#include <cuda_runtime.h>
#include <cuda_bf16.h>
#include <cstdint>
#include <stdint.h>
#include <math.h>

#define H      1024
#define FF     4096
#define E      8
#define T_MAX  8192
#define NROWS  (T_MAX * 2)
#define NROWSP 18432          // padded rows (per-expert base aligned to 256)
#define KC     32
#define TB     8192
#define NKC_H  (H / KC)       // 32  (== 0 mod 8)
#define NKC_F  (FF / KC)      // 128 (== 0 mod 8)
#define NST    4
#define NCTA   148

#if defined(__CUDA_ARCH_FEAT_SM103_ALL) || defined(__CUDA_ARCH_FEAT_SM100_ALL)
#define TC_OK 1
#else
#define TC_OK 0
#endif

// ---------------- device scratch ----------------
__device__ int   g_counts[E];
__device__ int   g_base[E];
__device__ int   g_pbase[E];
__device__ int   g_jb13[E];
__device__ int   g_J13;
__device__ int   g_jb2[E];
__device__ int   g_J2;
__device__ int   g_rdone;
__device__ int   g_list[E * T_MAX];
__device__ float g_wts[T_MAX * 2];
__device__ __nv_bfloat16 g_ax_hi[(size_t)NROWSP * H];
__device__ __nv_bfloat16 g_ax_lo[(size_t)NROWSP * H];
__device__ __nv_bfloat16 g_w1h[(size_t)E * FF * H];
__device__ __nv_bfloat16 g_w1l[(size_t)E * FF * H];
__device__ __nv_bfloat16 g_w3h[(size_t)E * FF * H];
__device__ __nv_bfloat16 g_w3l[(size_t)E * FF * H];
__device__ __nv_bfloat16 g_w2h[(size_t)E * H * FF];
__device__ __nv_bfloat16 g_w2l[(size_t)E * H * FF];
__device__ __nv_bfloat16 g_act_hi[(size_t)NROWSP * FF];
__device__ __nv_bfloat16 g_act_lo[(size_t)NROWSP * FF];
__device__ float g_ybuf[(size_t)NROWS * H];

// ---------------- PTX helpers ----------------
__device__ __forceinline__ uint32_t smem_u32(const void* p) {
    uint32_t a;
    asm("{ .reg .u64 t; cvta.to.shared.u64 t, %1; cvt.u32.u64 %0, t; }" : "=r"(a) : "l"(p));
    return a;
}
__device__ __forceinline__ uint32_t cta_rank() {
    uint32_t r; asm("mov.u32 %0, %%cluster_ctarank;" : "=r"(r)); return r;
}
#define MBAR_INIT(a, c) asm volatile("mbarrier.init.shared.b64 [%0], %1;" :: "r"((uint32_t)(a)), "r"((uint32_t)(c)) : "memory")
#define MBAR_EXPECT(a, n) asm volatile("mbarrier.arrive.expect_tx.shared.b64 _, [%0], %1;" :: "r"((uint32_t)(a)), "r"((uint32_t)(n)) : "memory")
#define MBAR_ARRIVE(a) asm volatile("mbarrier.arrive.shared.b64 _, [%0];" :: "r"((uint32_t)(a)) : "memory")
#define ARRIVE_REMOTE0(local) asm volatile("{\n\t.reg .b32 r;\n\tmapa.shared::cluster.u32 r, %0, 0;\n\tmbarrier.arrive.shared::cluster.b64 _, [r];\n\t}" :: "r"((uint32_t)(local)) : "memory")
#define CLUSTER_SYNC() do { \
    asm volatile("barrier.cluster.arrive.aligned;" ::: "memory"); \
    asm volatile("barrier.cluster.wait.aligned;" ::: "memory"); \
} while (0)
#define MBAR_WAIT(a, ph) do { \
    uint32_t _m = (uint32_t)(a), _p = (uint32_t)(ph), _d; \
    asm volatile("{\n\t.reg .pred p;\n\tmbarrier.try_wait.parity.acquire.cta.shared::cta.b64 p, [%1], %2;\n\tselp.b32 %0,1,0,p;\n\t}" \
        : "=r"(_d) : "r"(_m), "r"(_p) : "memory"); \
    if (!_d) { asm volatile("{\n\t.reg .pred P1;\n\tWL_%=:\n\t" \
        "mbarrier.try_wait.parity.acquire.cta.shared::cta.b64 P1, [%0], %1, 0x989680;\n\t" \
        "@P1 bra.uni WD_%=;\n\tbra.uni WL_%=;\n\tWD_%=:\n\t}" :: "r"(_m), "r"(_p) : "memory"); } \
} while (0)

#if TC_OK
#define BULK(d, s, mb) asm volatile( \
    "cp.async.bulk.shared::cta.global.mbarrier::complete_tx::bytes [%0], [%1], %2, [%3];" \
    :: "r"((uint32_t)(d)), "l"(s), "r"(8192u), "r"((uint32_t)(mb)) : "memory")
#define TC_ALLOC_CG2(sa, n)   asm volatile("tcgen05.alloc.cta_group::2.sync.aligned.shared::cta.b32 [%0], %1;" :: "r"((uint32_t)(sa)), "r"((uint32_t)(n)) : "memory")
#define TC_DEALLOC_CG2(tm, n) asm volatile("tcgen05.dealloc.cta_group::2.sync.aligned.b32 %0, %1;" :: "r"(tm), "r"((uint32_t)(n)))
#define TC_RELINQ_CG2()       asm volatile("tcgen05.relinquish_alloc_permit.cta_group::2.sync.aligned;")
#define TC_COMMIT_MC2(mb, mask) asm volatile( \
    "tcgen05.commit.cta_group::2.mbarrier::arrive::one.shared::cluster.multicast::cluster.b64 [%0], %1;" \
    :: "r"((uint32_t)(mb)), "h"((uint16_t)(mask)) : "memory")
#define TC_FENCE_AFTER()  asm volatile("tcgen05.fence::after_thread_sync;" ::: "memory")
#define TC_FENCE_BEFORE() asm volatile("tcgen05.fence::before_thread_sync;" ::: "memory")
#define TC_WAIT_LD()      asm volatile("tcgen05.wait::ld.sync.aligned;" ::: "memory")
#define TC_LD_X32(r, ta) \
    asm volatile("tcgen05.ld.sync.aligned.32x32b.x32.b32 " \
        "{%0,%1,%2,%3,%4,%5,%6,%7,%8,%9,%10,%11,%12,%13,%14,%15," \
        "%16,%17,%18,%19,%20,%21,%22,%23,%24,%25,%26,%27,%28,%29,%30,%31}, [%32];" \
        : "=r"((r)[0]), "=r"((r)[1]), "=r"((r)[2]), "=r"((r)[3]), "=r"((r)[4]), "=r"((r)[5]), "=r"((r)[6]), "=r"((r)[7]), \
          "=r"((r)[8]), "=r"((r)[9]), "=r"((r)[10]), "=r"((r)[11]), "=r"((r)[12]), "=r"((r)[13]), "=r"((r)[14]), "=r"((r)[15]), \
          "=r"((r)[16]), "=r"((r)[17]), "=r"((r)[18]), "=r"((r)[19]), "=r"((r)[20]), "=r"((r)[21]), "=r"((r)[22]), "=r"((r)[23]), \
          "=r"((r)[24]), "=r"((r)[25]), "=r"((r)[26]), "=r"((r)[27]), "=r"((r)[28]), "=r"((r)[29]), "=r"((r)[30]), "=r"((r)[31]) \
        : "r"(ta))

static constexpr uint64_t DESC_SW64 =
    (uint64_t(4) << 61) | (uint64_t(1) << 46) | (uint64_t(32) << 32) | (uint64_t(1) << 16);
#define MK_DESC(a) (DESC_SW64 | ((uint64_t)((a) >> 4) & 0x3FFF))
#define IDESC_CG2 ((1u << 4) | (1u << 7) | (1u << 10) | (32u << 17) | (16u << 24))

__device__ __forceinline__ void mma_cg2(uint32_t d, uint64_t a, uint64_t b, uint32_t en) {
    asm volatile("{\n\t.reg .pred p;\n\tsetp.ne.u32 p, %4, 0;\n\t"
        "tcgen05.mma.cta_group::2.kind::f16 [%0], %1, %2, %3, {%5,%5,%5,%5,%5,%5,%5,%5}, p;\n\t}"
        :: "r"(d), "l"(a), "l"(b), "r"(IDESC_CG2), "r"(en), "r"(0u) : "memory");
}
#endif  // TC_OK

__device__ __forceinline__ uint32_t pack_hi(float a, float b, uint32_t& lo) {
    __nv_bfloat16 h0 = __float2bfloat16(a), h1 = __float2bfloat16(b);
    __nv_bfloat16 l0 = __float2bfloat16(a - __bfloat162float(h0));
    __nv_bfloat16 l1 = __float2bfloat16(b - __bfloat162float(h1));
    lo = (uint32_t)__bfloat16_as_ushort(l0) | ((uint32_t)__bfloat16_as_ushort(l1) << 16);
    return (uint32_t)__bfloat16_as_ushort(h0) | ((uint32_t)__bfloat16_as_ushort(h1) << 16);
}

__device__ __forceinline__ void split8_body(const float* __restrict__ src,
                                            __nv_bfloat16* __restrict__ hi,
                                            __nv_bfloat16* __restrict__ lo,
                                            long i, int K, int nkc) {
    long f = i * 8;
    int row = (int)(f / K), k0 = (int)(f % K);
    int kc = k0 >> 5, c = (k0 & 31) >> 3;
    int rr = row & 127, tr = row >> 7;
    size_t off = ((size_t)tr * nkc + kc) * TB + (size_t)rr * 64 + ((c ^ ((rr >> 1) & 3)) << 4);
    const float4* s4 = (const float4*)(src + f);
    float4 a = s4[0], b = s4[1];
    float v[8] = {a.x, a.y, a.z, a.w, b.x, b.y, b.z, b.w};
    uint32_t ph[4], pl[4];
#pragma unroll
    for (int j = 0; j < 4; j++) ph[j] = pack_hi(v[2 * j], v[2 * j + 1], pl[j]);
    *(uint4*)((char*)hi + off) = make_uint4(ph[0], ph[1], ph[2], ph[3]);
    *(uint4*)((char*)lo + off) = make_uint4(pl[0], pl[1], pl[2], pl[3]);
}

// ---------------- fused split kernel + counts zeroing ----------------
__global__ void k_split_all(const float* __restrict__ w1, const float* __restrict__ w3,
                            const float* __restrict__ w2) {
    if (blockIdx.x == 0 && threadIdx.x < E) g_counts[threadIdx.x] = 0;
    if (blockIdx.x == 0 && threadIdx.x == 0) g_rdone = 0;
    const long n8 = (long)E * FF * H / 8;
    const long stride = (long)gridDim.x * blockDim.x;
    long i0 = (long)blockIdx.x * blockDim.x + threadIdx.x;
    for (long i = i0; i < n8; i += stride) {
        split8_body(w1, g_w1h, g_w1l, i, H, NKC_H);
        split8_body(w3, g_w3h, g_w3l, i, H, NKC_H);
        split8_body(w2, g_w2h, g_w2l, i, FF, NKC_F);
    }
}

// ---------------- router (+ last-block prefix/base) ----------------
__global__ void k_router(const float* __restrict__ x, const float* __restrict__ gate,
                         float* __restrict__ logits_out, int T) {
    __shared__ float sg[E * H];
    for (int i = threadIdx.x; i < E * H; i += blockDim.x) sg[i] = gate[i];
    __syncthreads();
    int warp = threadIdx.x >> 5, lane = threadIdx.x & 31;
    int t = blockIdx.x * 8 + warp;
    if (t < T) {
        const float* xr = x + (size_t)t * H;
        float acc[E];
#pragma unroll
        for (int e = 0; e < E; e++) acc[e] = 0.f;
        for (int k = lane; k < H; k += 32) {
            float xv = xr[k];
#pragma unroll
            for (int e = 0; e < E; e++) acc[e] += xv * sg[e * H + k];
        }
#pragma unroll
        for (int e = 0; e < E; e++)
#pragma unroll
            for (int o = 16; o > 0; o >>= 1) acc[e] += __shfl_down_sync(0xffffffffu, acc[e], o);
        if (lane == 0) {
#pragma unroll
            for (int e = 0; e < E; e++) logits_out[(size_t)t * E + e] = acc[e];
            int e0 = 0; float l0 = acc[0];
#pragma unroll
            for (int e = 1; e < E; e++) if (acc[e] > l0) { l0 = acc[e]; e0 = e; }
            int e1 = -1; float l1 = -1e30f;
#pragma unroll
            for (int e = 0; e < E; e++) if (e != e0 && acc[e] > l1) { l1 = acc[e]; e1 = e; }
            float s = 0.f, pe[E];
#pragma unroll
            for (int e = 0; e < E; e++) { pe[e] = expf(acc[e] - l0); s += pe[e]; }
            float p0 = pe[e0] / s, p1 = pe[e1] / s;
            float inv = 1.f / (p0 + p1);
            int q0 = atomicAdd(&g_counts[e0], 1);
            g_list[e0 * T_MAX + q0] = (t << 1);
            g_wts[(t << 1)] = p0 * inv;
            int q1 = atomicAdd(&g_counts[e1], 1);
            g_list[e1 * T_MAX + q1] = (t << 1) | 1;
            g_wts[(t << 1) | 1] = p1 * inv;
        }
    }
    __syncthreads();
    if (threadIdx.x == 0) {
        __threadfence();
        int done = atomicAdd(&g_rdone, 1);
        if (done == (int)gridDim.x - 1) {
            int s = 0, ps = 0, j13 = 0, j2 = 0;
#pragma unroll
            for (int e = 0; e < E; e++) {
                g_base[e] = s;  g_pbase[e] = ps;
                g_jb13[e] = j13; g_jb2[e] = j2;
                int np = (g_counts[e] + 255) >> 8;
                j13 += np * (FF / 128);
                j2  += np * (H / 256);
                s += g_counts[e];
                ps += (g_counts[e] + 255) & ~255;
            }
            g_J13 = j13;  g_J2 = j2;
        }
    }
}

// gather x rows into expert-grouped (padded) tiled hi/lo
__global__ void k_gather(const float* __restrict__ x, int total) {
    int g = blockIdx.x;
    if (g >= total) return;
    int e = 0;
#pragma unroll
    for (int k = 1; k < E; k++) if (g >= g_base[k]) e = k;
    int pos = g - g_base[e];
    int tok = g_list[e * T_MAX + pos] >> 1;
    int prow = g_pbase[e] + pos;
    int rr = prow & 127, tr = prow >> 7;
    int tid = threadIdx.x;
    int kc = tid >> 2, c = tid & 3;
    size_t off = ((size_t)tr * NKC_H + kc) * TB + (size_t)rr * 64 + ((c ^ ((rr >> 1) & 3)) << 4);
    const float4* src = (const float4*)(x + (size_t)tok * H + tid * 8);
    float4 a = src[0], b = src[1];
    uint32_t pl0, pl1, pl2, pl3;
    uint32_t ph0 = pack_hi(a.x, a.y, pl0);
    uint32_t ph1 = pack_hi(a.z, a.w, pl1);
    uint32_t ph2 = pack_hi(b.x, b.y, pl2);
    uint32_t ph3 = pack_hi(b.z, b.w, pl3);
    *(uint4*)((char*)g_ax_hi + off) = make_uint4(ph0, ph1, ph2, ph3);
    *(uint4*)((char*)g_ax_lo + off) = make_uint4(pl0, pl1, pl2, pl3);
}

#define SM_T 1024
#define MB_FULL(b) (8 + (b) * 8)
#define MB_DONE(b) (48 + (b) * 8)
#define MB_ACC(b)  (80 + (b) * 8)
#define MB_EPI(b)  (96 + (b) * 8)

#if TC_OK
__device__ __forceinline__ void bulk4(uint32_t sb, int buf,
    const __nv_bfloat16* Ah, const __nv_bfloat16* Al, int trA, int nkcA,
    const __nv_bfloat16* Wh, const __nv_bfloat16* Wl, int trW, int nkcW, int kc) {
    uint32_t mb = sb + MB_FULL(buf);
    uint32_t dst = sb + SM_T + buf * 4 * TB;
    size_t a0 = ((size_t)trA * nkcA + kc) * TB;
    size_t w  = ((size_t)trW * nkcW + kc) * TB;
    BULK(dst + 0 * TB, (const char*)Ah + a0, mb);
    BULK(dst + 1 * TB, (const char*)Al + a0, mb);
    BULK(dst + 2 * TB, (const char*)Wh + w, mb);
    BULK(dst + 3 * TB, (const char*)Wl + w, mb);
}

__device__ __forceinline__ int job_e(const int* jb, int j) {
    int e = 0;
#pragma unroll
    for (int k = 1; k < E; k++) if (j >= jb[k]) e = k;
    return e;
}

__device__ __forceinline__ void init_bars(uint32_t sb, int rank) {
#pragma unroll
    for (int b = 0; b < NST; b++) {
        MBAR_INIT(sb + MB_FULL(b), rank == 0 ? 2 : 1);  // producer expect (+ follower remote on leader)
        MBAR_INIT(sb + MB_DONE(b), 1);
    }
#pragma unroll
    for (int b = 0; b < 2; b++) {
        MBAR_INIT(sb + MB_ACC(b), 1);
        MBAR_INIT(sb + MB_EPI(b), 8);
    }
}

// producer warp (one thread): continuous chunk stream across jobs, 4 ahead
template <int IS13>
__device__ void producer(uint32_t sb, int pair, int npair, int J, int rank) {
    long s = 0;
    for (int j = pair; j < J; j += npair) {
        int e, trA, trW, nkc;
        const __nv_bfloat16 *Ah, *Al, *Wh, *Wl;
        if (IS13) {
            e = job_e(g_jb13, j);
            int local = j - g_jb13[e];
            trA = (g_pbase[e] + (local >> 5) * 256 + rank * 128) >> 7;
            trW = (e * FF + (local & 31) * 128) >> 7;
            Ah = g_ax_hi; Al = g_ax_lo;
            Wh = rank ? g_w3h : g_w1h;  Wl = rank ? g_w3l : g_w1l;
            nkc = NKC_H;
        } else {
            e = job_e(g_jb2, j);
            int local = j - g_jb2[e];
            trA = (g_pbase[e] + (local >> 2) * 256 + rank * 128) >> 7;
            trW = (e * H + (local & 3) * 256 + rank * 128) >> 7;
            Ah = g_act_hi; Al = g_act_lo;
            Wh = g_w2h; Wl = g_w2l;
            nkc = NKC_F;
        }
        int NCH = nkc;
        for (int i = 0; i < NCH; i++, s++) {
            int b = (int)(s & (NST - 1));
            if (s >= NST) MBAR_WAIT(sb + MB_DONE(b), (int)(((s - NST) >> 2) & 1));
            MBAR_EXPECT(sb + MB_FULL(b), 4 * TB);
            bulk4(sb, b, Ah, Al, trA, nkc, Wh, Wl, trW, nkc, i);
        }
    }
}
#endif

// ---------------- persistent cg2 GEMM kernel body (templated on phase) ----------------
#if TC_OK
template <int IS13>
__device__ void gemm_body() {
    int rank = (int)cta_rank();
    int pair = blockIdx.x >> 1;
    int npair = gridDim.x >> 1;
    extern __shared__ char sm[];
    uint32_t sb = smem_u32(sm);
    int tid = threadIdx.x, wid = tid >> 5, lid = tid & 31;

    if (wid == 0) TC_ALLOC_CG2(sb, 512);
    if (tid == 0) init_bars(sb, rank);
    __syncthreads();
    CLUSTER_SYNC();
    uint32_t tm;
    asm volatile("ld.shared.b32 %0, [%1];" : "=r"(tm) : "r"(sb));

    int J = IS13 ? g_J13 : g_J2;
    const int NCH = IS13 ? NKC_H : NKC_F;

    if (tid == 32) {
        producer<IS13>(sb, pair, npair, J, rank);
    } else if (tid == 0) {
        // consumer
        long s = 0;
        int jj = 0;
        for (int j = pair; j < J; j += npair, jj++) {
            uint32_t acc = tm + (jj & 1) * 256;
            if (rank == 0) {
                if (jj >= 2) { MBAR_WAIT(sb + MB_EPI(jj & 1), ((jj >> 1) - 1) & 1); }
                TC_FENCE_AFTER();
            }
            for (int i = 0; i < NCH; i++, s++) {
                int b = (int)(s & (NST - 1));
                MBAR_WAIT(sb + MB_FULL(b), (int)((s >> 2) & 1));
                if (rank == 0) {
                    uint32_t tb = sb + SM_T + b * 4 * TB;
                    uint64_t dAh = MK_DESC(tb),          dAl = MK_DESC(tb + TB);
                    uint64_t dWh = MK_DESC(tb + 2 * TB), dWl = MK_DESC(tb + 3 * TB);
#pragma unroll
                    for (int ks = 0; ks < 2; ks++) {
                        uint64_t o = (uint64_t)(2 * ks);
                        uint32_t en = (i > 0 || ks > 0) ? 1u : 0u;
                        mma_cg2(acc, dAh + o, dWh + o, en);
                        mma_cg2(acc, dAh + o, dWl + o, 1);
                        mma_cg2(acc, dAl + o, dWh + o, 1);
                    }
                    TC_COMMIT_MC2(sb + MB_DONE(b), 0x3);
                } else {
                    ARRIVE_REMOTE0(sb + MB_FULL(b));
                }
            }
            // drain last NST in-order commits of this job (covers all)
            for (long c = s - NST; c < s; c++)
                MBAR_WAIT(sb + MB_DONE((int)(c & (NST - 1))), (int)((c >> 2) & 1));
            MBAR_ARRIVE(sb + MB_ACC(jj & 1));
        }
    } else if (wid >= 4) {
        // epilogue crew (warps 4-7 -> subpartitions 0-3)
        int jj = 0;
        for (int j = pair; j < J; j += npair, jj++) {
            uint32_t acc = tm + (jj & 1) * 256;
            MBAR_WAIT(sb + MB_ACC(jj & 1), (jj >> 1) & 1);
            TC_FENCE_AFTER();
            int sub = wid - 4;
            int lrow = sub * 32 + lid;
            if (IS13) {
                int e = job_e(g_jb13, j);
                int local = j - g_jb13[e];
                int cnt = g_counts[e];
                int row0 = (local >> 5) * 256;
                int n0 = (local & 31) * 128;
                int rbase = g_pbase[e] + row0 + rank * 128;
                bool valid = (row0 + rank * 128 + lrow) < cnt;
                int prow = rbase + lrow;
                int rr = prow & 127, tr = prow >> 7, sw = (rr >> 1) & 3;
#pragma unroll
                for (int c0 = 0; c0 < 128; c0 += 32) {
                    uint32_t d1[32], d3[32];
                    TC_LD_X32(d1, acc + c0);
                    TC_LD_X32(d3, acc + 128 + c0);
                    TC_WAIT_LD();
                    if (valid) {
                        uint32_t ph[16], pl[16];
#pragma unroll
                        for (int jq = 0; jq < 16; jq++) {
                            float h0 = __uint_as_float(d1[2 * jq]),     v0 = __uint_as_float(d3[2 * jq]);
                            float h1 = __uint_as_float(d1[2 * jq + 1]), v1 = __uint_as_float(d3[2 * jq + 1]);
                            float a0 = (h0 / (1.f + __expf(-h0))) * v0;
                            float a1 = (h1 / (1.f + __expf(-h1))) * v1;
                            ph[jq] = pack_hi(a0, a1, pl[jq]);
                        }
                        int kc = (n0 >> 5) + (c0 >> 5);
                        size_t tbo = ((size_t)tr * NKC_F + kc) * TB + (size_t)rr * 64;
#pragma unroll
                        for (int q = 0; q < 4; q++) {
                            size_t o = tbo + ((q ^ sw) << 4);
                            *(uint4*)((char*)g_act_hi + o) = make_uint4(ph[4 * q], ph[4 * q + 1], ph[4 * q + 2], ph[4 * q + 3]);
                            *(uint4*)((char*)g_act_lo + o) = make_uint4(pl[4 * q], pl[4 * q + 1], pl[4 * q + 2], pl[4 * q + 3]);
                        }
                    }
                }
            } else {
                int e = job_e(g_jb2, j);
                int local = j - g_jb2[e];
                int cnt = g_counts[e];
                int row0 = (local >> 2) * 256;
                int n0 = (local & 3) * 256;
                bool valid = (row0 + rank * 128 + lrow) < cnt;
                int ts = 0; float w = 0.f;
                if (valid) { ts = g_list[e * T_MAX + row0 + rank * 128 + lrow]; w = g_wts[ts]; }
                float* yrow = g_ybuf + (size_t)ts * H + n0;
#pragma unroll
                for (int c0 = 0; c0 < 256; c0 += 32) {
                    uint32_t d[32];
                    TC_LD_X32(d, acc + c0);
                    TC_WAIT_LD();
                    if (valid) {
                        float4* dst = (float4*)(yrow + c0);
#pragma unroll
                        for (int q = 0; q < 8; q++)
                            dst[q] = make_float4(w * __uint_as_float(d[4 * q]), w * __uint_as_float(d[4 * q + 1]),
                                                 w * __uint_as_float(d[4 * q + 2]), w * __uint_as_float(d[4 * q + 3]));
                    }
                }
            }
            TC_FENCE_BEFORE();
            if (lid == 0) {
                if (rank == 0) MBAR_ARRIVE(sb + MB_EPI(jj & 1));
                else           ARRIVE_REMOTE0(sb + MB_EPI(jj & 1));
            }
        }
    }
    __syncthreads();
    if (wid == 0) { TC_RELINQ_CG2(); TC_DEALLOC_CG2(tm, 512); }
    CLUSTER_SYNC();
}
#endif

__global__ __launch_bounds__(256, 1) __cluster_dims__(2, 1, 1) void k_mma13() {
#if TC_OK
    gemm_body<1>();
#endif
}
__global__ __launch_bounds__(256, 1) __cluster_dims__(2, 1, 1) void k_mma2() {
#if TC_OK
    gemm_body<0>();
#endif
}

__global__ void k_combine(float* __restrict__ out, int T) {
    int i = blockIdx.x * blockDim.x + threadIdx.x;
    int total = T * (H / 4);
    if (i >= total) return;
    int t = i / (H / 4);
    int h4 = i - t * (H / 4);
    const float4* yb = (const float4*)g_ybuf;
    float4 a = yb[(size_t)(2 * t) * (H / 4) + h4];
    float4 b = yb[(size_t)(2 * t + 1) * (H / 4) + h4];
    ((float4*)out)[i] = make_float4(a.x + b.x, a.y + b.y, a.z + b.z, a.w + b.w);
}

// ---------------- launch ----------------
extern "C" void kernel_launch(void* const* d_in, const int* in_sizes, int n_in,
                              void* d_out, int out_size) {
    const float* x;
    const float* gate;
    if (in_sizes[0] > in_sizes[1]) { x = (const float*)d_in[0]; gate = (const float*)d_in[1]; }
    else                           { gate = (const float*)d_in[0]; x = (const float*)d_in[1]; }
    const float* w1 = (const float*)d_in[2];
    const float* w2 = (const float*)d_in[3];
    const float* w3 = (const float*)d_in[4];
    int T = (in_sizes[0] > in_sizes[1] ? in_sizes[0] : in_sizes[1]) / H;

    float* out = (float*)d_out;
    float* logits_out = out + (size_t)T * H;

    int smem = SM_T + NST * 4 * TB;  // 132,096
    cudaFuncSetAttribute(k_mma13, cudaFuncAttributeMaxDynamicSharedMemorySize, smem);
    cudaFuncSetAttribute(k_mma2,  cudaFuncAttributeMaxDynamicSharedMemorySize, smem);

    long n8 = (long)E * FF * H / 8;
    int sblk = (int)((n8 + 255) / 256);
    if (sblk > 16384) sblk = 16384;
    k_split_all<<<sblk, 256>>>(w1, w3, w2);

    k_router<<<(T + 7) / 8, 256>>>(x, gate, logits_out, T);
    k_gather<<<2 * T, 128>>>(x, 2 * T);

    cudaLaunchAttribute attrs[1];
    attrs[0].id = cudaLaunchAttributeClusterDimension;
    attrs[0].val.clusterDim.x = 2; attrs[0].val.clusterDim.y = 1; attrs[0].val.clusterDim.z = 1;

    cudaLaunchConfig_t cfg13 = {};
    cfg13.gridDim  = dim3(NCTA, 1, 1);
    cfg13.blockDim = dim3(256, 1, 1);
    cfg13.dynamicSmemBytes = smem;
    cfg13.attrs = attrs; cfg13.numAttrs = 1;
    cudaLaunchKernelEx(&cfg13, k_mma13);

    cudaLaunchConfig_t cfg2 = {};
    cfg2.gridDim  = dim3(NCTA, 1, 1);
    cfg2.blockDim = dim3(256, 1, 1);
    cfg2.dynamicSmemBytes = smem;
    cfg2.attrs = attrs; cfg2.numAttrs = 1;
    cudaLaunchKernelEx(&cfg2, k_mma2);

    k_combine<<<(T * (H / 4) + 255) / 256, 256>>>(out, T);
}